// round 3
// baseline (speedup 1.0000x reference)
#include <cuda_runtime.h>

// Apply2DDispField: bilinear warp of Img (B,H,W,1) by DispField (B,H,W,2).
//
// Coordinate math uses explicit __fmul_rn/__fadd_rn in the reference's exact
// op order so the floor()/clip corner selection is bitwise-identical to the
// XLA fp32 reference (no FFMA contraction — the sampler has a genuine
// discontinuity at x=0/y=0 where 1-ulp differences flip output by O(1)).
//
// Memory strategy: DispField & out are streamed (evict-first .cs) so the
// 64 MB Img working set stays resident in L2 for the random gathers.

#define BB 16
#define HH 1024
#define WW 1024

__global__ __launch_bounds__(256) void apply_disp_kernel(
    const float* __restrict__ img,
    const float* __restrict__ disp,
    float* __restrict__ out)
{
    const int tid = blockIdx.x * blockDim.x + threadIdx.x;   // one thread = 4 pixels
    const long long base = (long long)tid * 4;               // linear pixel index

    const int j0 = (int)(base & (WW - 1));
    const int i  = (int)((base >> 10) & (HH - 1));
    const int b  = (int)(base >> 20);

    const float* imgb = img + ((size_t)b << 20);

    // DispField: 2 floats/pixel -> 4 pixels = 2 float4 loads (streaming)
    const float4* dptr = (const float4*)disp + (size_t)tid * 2;
    float4 dA = __ldcs(dptr);      // pixels j0, j0+1 : (d0x,d0y,d1x,d1y)
    float4 dB = __ldcs(dptr + 1);  // pixels j0+2, j0+3

    // linspace(-1,1,1024)[i] = -1 + i * (2/1023), separate rn mul + rn add
    const float step = 2.0f / 1023.0f;                       // fp32 rn constant
    const float ax = __fadd_rn(-1.0f, __fmul_rn((float)i, step));

    float dx[4] = {dA.x, dA.z, dB.x, dB.z};
    float dy[4] = {dA.y, dA.w, dB.y, dB.w};

    float r[4];
#pragma unroll
    for (int p = 0; p < 4; ++p) {
        const int jj = j0 + p;
        const float ay = __fadd_rn(-1.0f, __fmul_rn((float)jj, step));

        // reference order: x_s = ax - d; x = (0.5*(x_s+1))*1023, all rn, no fma
        const float xs = __fadd_rn(ax, -dx[p]);
        const float ys = __fadd_rn(ay, -dy[p]);
        const float x  = __fmul_rn(__fmul_rn(0.5f, __fadd_rn(xs, 1.0f)), 1023.0f);
        const float y  = __fmul_rn(__fmul_rn(0.5f, __fadd_rn(ys, 1.0f)), 1023.0f);

        const float x0f = floorf(x);
        const float y0f = floorf(y);

        int x0 = (int)x0f;                        x0 = min(max(x0, 0), 1024);
        int x1 = (int)__fadd_rn(x0f, 1.0f);       x1 = min(max(x1, 0), 1024);
        int y0 = (int)y0f;                        y0 = min(max(y0, 0), 1024);
        int y1 = (int)__fadd_rn(y0f, 1.0f);       y1 = min(max(y1, 0), 1024);

        // padded image: row/col index 1024 is the zero pad
        const bool x0in = (x0 < HH), x1in = (x1 < HH);
        const bool y0in = (y0 < WW), y1in = (y1 < WW);

        const float* row0 = imgb + ((size_t)x0 << 10);
        const float* row1 = imgb + ((size_t)x1 << 10);

        const float I00 = (x0in && y0in) ? __ldg(row0 + y0) : 0.0f;
        const float I01 = (x0in && y1in) ? __ldg(row0 + y1) : 0.0f;
        const float I10 = (x1in && y0in) ? __ldg(row1 + y0) : 0.0f;
        const float I11 = (x1in && y1in) ? __ldg(row1 + y1) : 0.0f;

        // weights from clamped integer corners, separate rn ops (match ref)
        const float wx1 = __fadd_rn((float)x1, -x);   // (x1c - x)
        const float wx0 = __fadd_rn(x, -(float)x0);   // (x - x0c)
        const float wy1 = __fadd_rn((float)y1, -y);
        const float wy0 = __fadd_rn(y, -(float)y0);

        const float W00 = __fmul_rn(wx1, wy1);
        const float W01 = __fmul_rn(wx1, wy0);
        const float W10 = __fmul_rn(wx0, wy1);
        const float W11 = __fmul_rn(wx0, wy0);

        r[p] = __fadd_rn(
                 __fadd_rn(__fmul_rn(W00, I00), __fmul_rn(W01, I01)),
                 __fadd_rn(__fmul_rn(W10, I10), __fmul_rn(W11, I11)));
    }

    float4 res = make_float4(r[0], r[1], r[2], r[3]);
    __stcs((float4*)out + tid, res);
}

extern "C" void kernel_launch(void* const* d_in, const int* in_sizes, int n_in,
                              void* d_out, int out_size)
{
    const float* img  = (const float*)d_in[0];   // (16,1024,1024,1) fp32
    const float* disp = (const float*)d_in[1];   // (16,1024,1024,2) fp32
    float* out = (float*)d_out;                  // (16,1024,1024,1) fp32

    const long long total_pixels = (long long)BB * HH * WW;   // 16,777,216
    const int threads = (int)(total_pixels / 4);              // 4,194,304
    const int block = 256;
    const int grid = threads / block;                          // 16,384

    apply_disp_kernel<<<grid, block>>>(img, disp, out);
}

// round 4
// speedup vs baseline: 1.0807x; 1.0807x over previous
#include <cuda_runtime.h>

// Apply2DDispField: bilinear warp of Img (B,H,W,1) by DispField (B,H,W,2).
//
// Corner-selection math uses explicit __fmul_rn/__fadd_rn in the reference's
// exact op order (bitwise-matching the XLA fp32 reference; the sampler is
// discontinuous at the clamp boundary, so 1-ulp differences flip outputs).
//
// Perf: L1tex-wavefront-bound (R3 ncu: L1=84%, DRAM=31%). The two column
// texels of each row (y0, y1=y0+1 or y0) share one aligned 16B quad in 75%+
// of lanes, so each row uses ONE divergent LDG.128 + a predicated scalar
// fallback instead of two scalar gathers: ~2.5 gather-wavefront-units per
// pixel instead of 4.
//
// DispField & out are streamed (.cs evict-first) so the 64 MB Img stays
// L2-resident for the gathers.

#define BB 16
#define HH 1024
#define WW 1024

// dynamic extract of element t (0..3) from a float4: 2-level select
__device__ __forceinline__ float sel4(float4 v, int t) {
    const float a = (t & 2) ? v.z : v.x;
    const float b = (t & 2) ? v.w : v.y;
    return (t & 1) ? b : a;
}

__global__ __launch_bounds__(256) void apply_disp_kernel(
    const float* __restrict__ img,
    const float* __restrict__ disp,
    float* __restrict__ out)
{
    const int tid = blockIdx.x * blockDim.x + threadIdx.x;   // one thread = 4 pixels
    const long long base = (long long)tid * 4;               // linear pixel index

    const int j0 = (int)(base & (WW - 1));
    const int i  = (int)((base >> 10) & (HH - 1));
    const int b  = (int)(base >> 20);

    const float* imgb = img + ((size_t)b << 20);

    // DispField: 2 floats/pixel -> 4 pixels = 2 float4 loads (streaming)
    const float4* dptr = (const float4*)disp + (size_t)tid * 2;
    float4 dA = __ldcs(dptr);      // pixels j0, j0+1 : (d0x,d0y,d1x,d1y)
    float4 dB = __ldcs(dptr + 1);  // pixels j0+2, j0+3

    // linspace(-1,1,1024)[i] = -1 + i*(2/1023), separate rn mul + rn add
    const float step = 2.0f / 1023.0f;
    const float ax = __fadd_rn(-1.0f, __fmul_rn((float)i, step));

    float dx[4] = {dA.x, dA.z, dB.x, dB.z};
    float dy[4] = {dA.y, dA.w, dB.y, dB.w};

    float r[4];
#pragma unroll
    for (int p = 0; p < 4; ++p) {
        const int jj = j0 + p;
        const float ay = __fadd_rn(-1.0f, __fmul_rn((float)jj, step));

        // reference order: x_s = ax - d; x = (0.5*(x_s+1))*1023, all rn, no fma
        const float xs = __fadd_rn(ax, -dx[p]);
        const float ys = __fadd_rn(ay, -dy[p]);
        const float x  = __fmul_rn(__fmul_rn(0.5f, __fadd_rn(xs, 1.0f)), 1023.0f);
        const float y  = __fmul_rn(__fmul_rn(0.5f, __fadd_rn(ys, 1.0f)), 1023.0f);

        const float x0f = floorf(x);
        const float y0f = floorf(y);

        int x0 = (int)x0f;                  x0 = min(max(x0, 0), 1024);
        int x1 = (int)__fadd_rn(x0f, 1.0f); x1 = min(max(x1, 0), 1024);
        int y0 = (int)y0f;                  y0 = min(max(y0, 0), 1024);
        int y1 = (int)__fadd_rn(y0f, 1.0f); y1 = min(max(y1, 0), 1024);

        // padded image: row/col index 1024 reads the zero pad
        const bool r0 = (x0 < HH), r1 = (x1 < HH);
        const bool c0 = (y0 < WW), c1 = (y1 < WW);
        const int  s1 = y1 - y0;            // 0 (clamped) or 1
        // note: c0 false => y0==1024 => y1==1024 => c1 false

        float I00 = 0.0f, I01 = 0.0f, I10 = 0.0f, I11 = 0.0f;

        const float* row0 = imgb + ((size_t)x0 << 10);
        const float* row1 = imgb + ((size_t)x1 << 10);
        const int q = y0 >> 2;
        const int s = y0 & 3;
        const int t = s + s1;               // element index of y1 within quad (if <=3)

        if (r0 & c0) {
            const float4 v = __ldg((const float4*)row0 + q);
            I00 = sel4(v, s);
            if (c1) {
                if (t <= 3) I01 = sel4(v, t);
                else        I01 = __ldg(row0 + y1);   // straddles quad: ~25% lanes
            }
        }
        if (r1 & c0) {
            const float4 w = __ldg((const float4*)row1 + q);
            I10 = sel4(w, s);
            if (c1) {
                if (t <= 3) I11 = sel4(w, t);
                else        I11 = __ldg(row1 + y1);
            }
        }

        // weights from clamped integer corners, separate rn ops (match ref)
        const float wx1 = __fadd_rn((float)x1, -x);
        const float wx0 = __fadd_rn(x, -(float)x0);
        const float wy1 = __fadd_rn((float)y1, -y);
        const float wy0 = __fadd_rn(y, -(float)y0);

        const float W00 = __fmul_rn(wx1, wy1);
        const float W01 = __fmul_rn(wx1, wy0);
        const float W10 = __fmul_rn(wx0, wy1);
        const float W11 = __fmul_rn(wx0, wy0);

        r[p] = __fadd_rn(
                 __fadd_rn(__fmul_rn(W00, I00), __fmul_rn(W01, I01)),
                 __fadd_rn(__fmul_rn(W10, I10), __fmul_rn(W11, I11)));
    }

    float4 res = make_float4(r[0], r[1], r[2], r[3]);
    __stcs((float4*)out + tid, res);
}

extern "C" void kernel_launch(void* const* d_in, const int* in_sizes, int n_in,
                              void* d_out, int out_size)
{
    const float* img  = (const float*)d_in[0];   // (16,1024,1024,1) fp32
    const float* disp = (const float*)d_in[1];   // (16,1024,1024,2) fp32
    float* out = (float*)d_out;                  // (16,1024,1024,1) fp32

    const long long total_pixels = (long long)BB * HH * WW;   // 16,777,216
    const int threads = (int)(total_pixels / 4);              // 4,194,304
    const int block = 256;
    const int grid = threads / block;                          // 16,384

    apply_disp_kernel<<<grid, block>>>(img, disp, out);
}